// round 13
// baseline (speedup 1.0000x reference)
#include <cuda_runtime.h>

#define B 4
#define T 1024
#define E 512
#define H 8
#define L 4
#define V 32000
#define HID 100
#define HD 64
#define BT (B*T)

// ---------------- scratch (no allocations allowed) ----------------
__device__ float g_x[BT * E];
__device__ float g_h[BT * E];
__device__ float g_q[BT * E];
__device__ float g_k[BT * E];
__device__ float g_v[BT * E];
__device__ float g_y[BT * E];
__device__ float g_f[BT * HID];

// ---------------- embedding: x = tok_emb[idx] + pos_emb ----------------
__global__ void embed_kernel(const int* __restrict__ idx,
                             const float* __restrict__ tok,
                             const float* __restrict__ pos,
                             float* __restrict__ x) {
    int i = blockIdx.x * 256 + threadIdx.x;      // i < BT*E
    int e = i & (E - 1);
    int bt = i >> 9;                              // E = 512
    int t = bt & (T - 1);                         // T = 1024
    x[i] = tok[(size_t)idx[bt] * E + e] + pos[t * E + e];
}

// ---------------- layernorm: one block per row of E=512 ----------------
__global__ void ln_kernel(const float* __restrict__ x,
                          const float* __restrict__ g,
                          const float* __restrict__ b,
                          float* __restrict__ o) {
    int row = blockIdx.x;
    int tid = threadIdx.x;
    const float* xr = x + (size_t)row * E;
    float v0 = xr[tid], v1 = xr[tid + 256];
    __shared__ float red[256];
    red[tid] = v0 + v1;
    __syncthreads();
    #pragma unroll
    for (int s = 128; s > 0; s >>= 1) {
        if (tid < s) red[tid] += red[tid + s];
        __syncthreads();
    }
    float m = red[0] * (1.0f / E);
    __syncthreads();
    float d0 = v0 - m, d1 = v1 - m;
    red[tid] = d0 * d0 + d1 * d1;
    __syncthreads();
    #pragma unroll
    for (int s = 128; s > 0; s >>= 1) {
        if (tid < s) red[tid] += red[tid + s];
        __syncthreads();
    }
    float rstd = rsqrtf(red[0] * (1.0f / E) + 1e-5f);
    float* orow = o + (size_t)row * E;
    orow[tid]       = d0 * rstd * g[tid]       + b[tid];
    orow[tid + 256] = d1 * rstd * g[tid + 256] + b[tid + 256];
}

// ---------------- generic tiled GEMM: C = A[MxK] @ W[KxN] (+bias)(+relu)(+resid) ----------------
// 64x64 tile, 256 threads, 4x4 microtile. flags: 1=bias, 2=relu, 4=residual add.
__global__ void gemm_kernel(const float* __restrict__ A,
                            const float* __restrict__ W,
                            const float* __restrict__ bias,
                            const float* __restrict__ resid,
                            float* __restrict__ C,
                            int M, int N, int K, int flags) {
    __shared__ float As[64][17];   // [row][kk], padded
    __shared__ float Ws[16][64];   // [kk][col]
    int tid = threadIdx.x;
    int rowBase = blockIdx.y * 64;
    int colBase = blockIdx.x * 64;
    int r0 = (tid >> 4) * 4;
    int c0 = (tid & 15) * 4;
    float acc[4][4] = {};

    for (int k0 = 0; k0 < K; k0 += 16) {
        #pragma unroll
        for (int i = 0; i < 4; i++) {
            int e = tid + i * 256;
            int r = e >> 4, kk = e & 15;
            int gk = k0 + kk;
            As[r][kk] = (gk < K) ? A[(size_t)(rowBase + r) * K + gk] : 0.f;
        }
        #pragma unroll
        for (int i = 0; i < 4; i++) {
            int e = tid + i * 256;
            int kk = e >> 6, cc = e & 63;
            int gk = k0 + kk, gc = colBase + cc;
            Ws[kk][cc] = (gk < K && gc < N) ? W[(size_t)gk * N + gc] : 0.f;
        }
        __syncthreads();
        #pragma unroll
        for (int kk = 0; kk < 16; kk++) {
            float a0 = As[r0 + 0][kk];
            float a1 = As[r0 + 1][kk];
            float a2 = As[r0 + 2][kk];
            float a3 = As[r0 + 3][kk];
            float4 bb = *(const float4*)&Ws[kk][c0];
            acc[0][0] += a0 * bb.x; acc[0][1] += a0 * bb.y; acc[0][2] += a0 * bb.z; acc[0][3] += a0 * bb.w;
            acc[1][0] += a1 * bb.x; acc[1][1] += a1 * bb.y; acc[1][2] += a1 * bb.z; acc[1][3] += a1 * bb.w;
            acc[2][0] += a2 * bb.x; acc[2][1] += a2 * bb.y; acc[2][2] += a2 * bb.z; acc[2][3] += a2 * bb.w;
            acc[3][0] += a3 * bb.x; acc[3][1] += a3 * bb.y; acc[3][2] += a3 * bb.z; acc[3][3] += a3 * bb.w;
        }
        __syncthreads();
    }

    #pragma unroll
    for (int i = 0; i < 4; i++) {
        int gr = rowBase + r0 + i;
        #pragma unroll
        for (int j = 0; j < 4; j++) {
            int gc = colBase + c0 + j;
            if (gc < N) {
                float val = acc[i][j];
                if (flags & 1) val += bias[gc];
                if (flags & 2) val = fmaxf(val, 0.f);
                if (flags & 4) val += resid[(size_t)gr * N + gc];
                C[(size_t)gr * N + gc] = val;
            }
        }
    }
}

// ---------------- attention scores: S = Q K^T * scale (causal; write only valid) ----------------
// grid (ct=16, rt=16, bh=32); writes into per-layer slab of d_out.
__global__ void scores_kernel(const float* __restrict__ q,
                              const float* __restrict__ k,
                              float* __restrict__ attn) {
    int bh = blockIdx.z;
    int b = bh >> 3, h = bh & 7;
    int rt = blockIdx.y, ct = blockIdx.x;
    if (ct > rt) return;   // fully masked tile: softmax writes the zeros
    __shared__ float Qs[64][65];   // [r][d]
    __shared__ float Kt[64][68];   // [d][c]
    int tid = threadIdx.x;
    int rowBase = rt * 64, colBase = ct * 64;
    const float* qb = q + ((size_t)(b * T + rowBase)) * E + h * HD;
    const float* kb = k + ((size_t)(b * T + colBase)) * E + h * HD;
    #pragma unroll
    for (int i = 0; i < 16; i++) {
        int e = tid + i * 256;
        int d = e & 63, r = e >> 6;
        Qs[r][d] = qb[(size_t)r * E + d];
        Kt[d][r] = kb[(size_t)r * E + d];
    }
    __syncthreads();
    int r0 = (tid >> 4) * 4, c0 = (tid & 15) * 4;
    float acc[4][4] = {};
    #pragma unroll 16
    for (int d = 0; d < 64; d++) {
        float a0 = Qs[r0 + 0][d];
        float a1 = Qs[r0 + 1][d];
        float a2 = Qs[r0 + 2][d];
        float a3 = Qs[r0 + 3][d];
        float4 bb = *(const float4*)&Kt[d][c0];
        acc[0][0] += a0 * bb.x; acc[0][1] += a0 * bb.y; acc[0][2] += a0 * bb.z; acc[0][3] += a0 * bb.w;
        acc[1][0] += a1 * bb.x; acc[1][1] += a1 * bb.y; acc[1][2] += a1 * bb.z; acc[1][3] += a1 * bb.w;
        acc[2][0] += a2 * bb.x; acc[2][1] += a2 * bb.y; acc[2][2] += a2 * bb.z; acc[2][3] += a2 * bb.w;
        acc[3][0] += a3 * bb.x; acc[3][1] += a3 * bb.y; acc[3][2] += a3 * bb.z; acc[3][3] += a3 * bb.w;
    }
    const float sc = 0.125f;   // 1/sqrt(64)
    float* ab = attn + ((size_t)bh * T + rowBase) * T + colBase;
    #pragma unroll
    for (int i = 0; i < 4; i++) {
        int gr = rowBase + r0 + i;
        #pragma unroll
        for (int j = 0; j < 4; j++) {
            int gc = colBase + c0 + j;
            if (gc <= gr) ab[(size_t)(r0 + i) * T + c0 + j] = acc[i][j] * sc;
        }
    }
}

// ---------------- causal softmax in place; zeros masked tail ----------------
__global__ void softmax_kernel(float* __restrict__ attn) {
    int row = blockIdx.x;                  // over B*H*T
    int t = row & (T - 1);
    float* p = attn + (size_t)row * T;
    int valid = t + 1;
    __shared__ float red[256];
    int tid = threadIdx.x;
    float m = -1e30f;
    for (int j = tid; j < valid; j += 256) m = fmaxf(m, p[j]);
    red[tid] = m;
    __syncthreads();
    #pragma unroll
    for (int s = 128; s > 0; s >>= 1) {
        if (tid < s) red[tid] = fmaxf(red[tid], red[tid + s]);
        __syncthreads();
    }
    m = red[0];
    __syncthreads();
    float sum = 0.f;
    for (int j = tid; j < valid; j += 256) {
        float ev = __expf(p[j] - m);
        p[j] = ev;
        sum += ev;
    }
    red[tid] = sum;
    __syncthreads();
    #pragma unroll
    for (int s = 128; s > 0; s >>= 1) {
        if (tid < s) red[tid] += red[tid + s];
        __syncthreads();
    }
    float inv = 1.0f / red[0];
    for (int j = tid; j < valid; j += 256) p[j] *= inv;
    for (int j = valid + tid; j < T; j += 256) p[j] = 0.f;
}

// ---------------- Y = P @ V per (b,h); exploits causality (skip zero K-chunks) ----------------
// grid (rt=16, bh=32)
__global__ void av_kernel(const float* __restrict__ attn,
                          const float* __restrict__ v,
                          float* __restrict__ y) {
    int bh = blockIdx.y;
    int b = bh >> 3, h = bh & 7;
    int rt = blockIdx.x;
    int rowBase = rt * 64;
    __shared__ float Ps[64][65];   // [r][kk]
    __shared__ float Vs[64][68];   // [kk][c]
    int tid = threadIdx.x;
    int r0 = (tid >> 4) * 4, c0 = (tid & 15) * 4;
    float acc[4][4] = {};
    const float* ab = attn + ((size_t)bh * T + rowBase) * T;
    const float* vb = v + ((size_t)(b * T)) * E + h * HD;
    int kend = rowBase + 64;
    for (int k0 = 0; k0 < kend; k0 += 64) {
        #pragma unroll
        for (int i = 0; i < 16; i++) {
            int e = tid + i * 256;
            int cc = e & 63, rr = e >> 6;
            Ps[rr][cc] = ab[(size_t)rr * T + k0 + cc];
            Vs[rr][cc] = vb[(size_t)(k0 + rr) * E + cc];
        }
        __syncthreads();
        #pragma unroll 16
        for (int kk = 0; kk < 64; kk++) {
            float a0 = Ps[r0 + 0][kk];
            float a1 = Ps[r0 + 1][kk];
            float a2 = Ps[r0 + 2][kk];
            float a3 = Ps[r0 + 3][kk];
            float4 bb = *(const float4*)&Vs[kk][c0];
            acc[0][0] += a0 * bb.x; acc[0][1] += a0 * bb.y; acc[0][2] += a0 * bb.z; acc[0][3] += a0 * bb.w;
            acc[1][0] += a1 * bb.x; acc[1][1] += a1 * bb.y; acc[1][2] += a1 * bb.z; acc[1][3] += a1 * bb.w;
            acc[2][0] += a2 * bb.x; acc[2][1] += a2 * bb.y; acc[2][2] += a2 * bb.z; acc[2][3] += a2 * bb.w;
            acc[3][0] += a3 * bb.x; acc[3][1] += a3 * bb.y; acc[3][2] += a3 * bb.z; acc[3][3] += a3 * bb.w;
        }
        __syncthreads();
    }
    float* yb = y + ((size_t)(b * T + rowBase)) * E + h * HD;
    #pragma unroll
    for (int i = 0; i < 4; i++)
        #pragma unroll
        for (int j = 0; j < 4; j++)
            yb[(size_t)(r0 + i) * E + c0 + j] = acc[i][j];
}

// ---------------- launch ----------------
extern "C" void kernel_launch(void* const* d_in, const int* in_sizes, int n_in,
                              void* d_out, int out_size) {
    const int*   idx  = (const int*)  d_in[0];
    const float* tok  = (const float*)d_in[1];
    const float* pos  = (const float*)d_in[2];
    const float* ln1g = (const float*)d_in[3];
    const float* ln1b = (const float*)d_in[4];
    const float* Wq   = (const float*)d_in[5];
    const float* Wk   = (const float*)d_in[6];
    const float* Wv   = (const float*)d_in[7];
    const float* Wo   = (const float*)d_in[8];
    const float* bo   = (const float*)d_in[9];
    const float* ln2g = (const float*)d_in[10];
    const float* ln2b = (const float*)d_in[11];
    const float* W1   = (const float*)d_in[12];
    const float* b1   = (const float*)d_in[13];
    const float* W2   = (const float*)d_in[14];
    const float* b2   = (const float*)d_in[15];
    const float* lnfg = (const float*)d_in[16];
    const float* lnfb = (const float*)d_in[17];
    const float* Wlm  = (const float*)d_in[18];

    float* out = (float*)d_out;
    float* logits = out;                               // (B,T,V)
    float* attn_all = out + (size_t)B * T * V;         // (L,B,H,T,T)

    float *x, *h, *q, *kk, *v, *y, *f;
    cudaGetSymbolAddress((void**)&x,  g_x);
    cudaGetSymbolAddress((void**)&h,  g_h);
    cudaGetSymbolAddress((void**)&q,  g_q);
    cudaGetSymbolAddress((void**)&kk, g_k);
    cudaGetSymbolAddress((void**)&v,  g_v);
    cudaGetSymbolAddress((void**)&y,  g_y);
    cudaGetSymbolAddress((void**)&f,  g_f);

    embed_kernel<<<BT * E / 256, 256>>>(idx, tok, pos, x);

    dim3 gE((E + 63) / 64, BT / 64);
    dim3 gH((HID + 63) / 64, BT / 64);
    dim3 gV((V + 63) / 64, BT / 64);

    for (int l = 0; l < L; l++) {
        float* attn_l = attn_all + (size_t)l * B * H * T * T;
        ln_kernel<<<BT, 256>>>(x, ln1g + l * E, ln1b + l * E, h);
        gemm_kernel<<<gE, 256>>>(h, Wq + (size_t)l * E * E, nullptr, nullptr, q,  BT, E, E, 0);
        gemm_kernel<<<gE, 256>>>(h, Wk + (size_t)l * E * E, nullptr, nullptr, kk, BT, E, E, 0);
        gemm_kernel<<<gE, 256>>>(h, Wv + (size_t)l * E * E, nullptr, nullptr, v,  BT, E, E, 0);
        scores_kernel<<<dim3(T / 64, T / 64, B * H), 256>>>(q, kk, attn_l);
        softmax_kernel<<<B * H * T, 256>>>(attn_l);
        av_kernel<<<dim3(T / 64, B * H), 256>>>(attn_l, v, y);
        gemm_kernel<<<gE, 256>>>(y, Wo + (size_t)l * E * E, bo + l * E, x, x, BT, E, E, 1 | 4);
        ln_kernel<<<BT, 256>>>(x, ln2g + l * E, ln2b + l * E, h);
        gemm_kernel<<<gH, 256>>>(h, W1 + (size_t)l * E * HID, b1 + l * HID, nullptr, f, BT, HID, E, 1 | 2);
        gemm_kernel<<<gE, 256>>>(f, W2 + (size_t)l * HID * E, b2 + l * E, x, x, BT, E, HID, 1 | 4);
    }
    ln_kernel<<<BT, 256>>>(x, lnfg, lnfb, h);
    gemm_kernel<<<gV, 256>>>(h, Wlm, nullptr, nullptr, logits, BT, V, E, 0);
}

// round 14
// speedup vs baseline: 1.0010x; 1.0010x over previous
#include <cuda_runtime.h>

#define B 4
#define T 1024
#define E 512
#define H 8
#define L 4
#define V 32000
#define HID 100
#define HD 64
#define BT (B*T)

// ---------------- scratch (no allocations allowed) ----------------
__device__ float g_x[BT * E];
__device__ float g_h[BT * E];
__device__ float g_q[BT * E];
__device__ float g_k[BT * E];
__device__ float g_v[BT * E];
__device__ float g_y[BT * E];
__device__ float g_f[BT * HID];

// ---------------- embedding: x = tok_emb[idx] + pos_emb ----------------
__global__ void embed_kernel(const int* __restrict__ idx,
                             const float* __restrict__ tok,
                             const float* __restrict__ pos,
                             float* __restrict__ x) {
    int i = blockIdx.x * 256 + threadIdx.x;      // i < BT*E
    int e = i & (E - 1);
    int bt = i >> 9;                              // E = 512
    int t = bt & (T - 1);                         // T = 1024
    x[i] = tok[(size_t)idx[bt] * E + e] + pos[t * E + e];
}

// ---------------- layernorm: one block per row of E=512 ----------------
__global__ void ln_kernel(const float* __restrict__ x,
                          const float* __restrict__ g,
                          const float* __restrict__ b,
                          float* __restrict__ o) {
    int row = blockIdx.x;
    int tid = threadIdx.x;
    const float* xr = x + (size_t)row * E;
    float v0 = xr[tid], v1 = xr[tid + 256];
    __shared__ float red[256];
    red[tid] = v0 + v1;
    __syncthreads();
    #pragma unroll
    for (int s = 128; s > 0; s >>= 1) {
        if (tid < s) red[tid] += red[tid + s];
        __syncthreads();
    }
    float m = red[0] * (1.0f / E);
    __syncthreads();
    float d0 = v0 - m, d1 = v1 - m;
    red[tid] = d0 * d0 + d1 * d1;
    __syncthreads();
    #pragma unroll
    for (int s = 128; s > 0; s >>= 1) {
        if (tid < s) red[tid] += red[tid + s];
        __syncthreads();
    }
    float rstd = rsqrtf(red[0] * (1.0f / E) + 1e-5f);
    float* orow = o + (size_t)row * E;
    orow[tid]       = d0 * rstd * g[tid]       + b[tid];
    orow[tid + 256] = d1 * rstd * g[tid + 256] + b[tid + 256];
}

// ---------------- generic tiled GEMM: C = A[MxK] @ W[KxN] (+bias)(+relu)(+resid) ----------------
// 64x64 tile, 256 threads, 4x4 microtile. flags: 1=bias, 2=relu, 4=residual add.
__global__ void gemm_kernel(const float* __restrict__ A,
                            const float* __restrict__ W,
                            const float* __restrict__ bias,
                            const float* __restrict__ resid,
                            float* __restrict__ C,
                            int M, int N, int K, int flags) {
    __shared__ float As[64][17];   // [row][kk], padded
    __shared__ float Ws[16][64];   // [kk][col]
    int tid = threadIdx.x;
    int rowBase = blockIdx.y * 64;
    int colBase = blockIdx.x * 64;
    int r0 = (tid >> 4) * 4;
    int c0 = (tid & 15) * 4;
    float acc[4][4] = {};

    for (int k0 = 0; k0 < K; k0 += 16) {
        #pragma unroll
        for (int i = 0; i < 4; i++) {
            int e = tid + i * 256;
            int r = e >> 4, kk = e & 15;
            int gk = k0 + kk;
            As[r][kk] = (gk < K) ? A[(size_t)(rowBase + r) * K + gk] : 0.f;
        }
        #pragma unroll
        for (int i = 0; i < 4; i++) {
            int e = tid + i * 256;
            int kk = e >> 6, cc = e & 63;
            int gk = k0 + kk, gc = colBase + cc;
            Ws[kk][cc] = (gk < K && gc < N) ? W[(size_t)gk * N + gc] : 0.f;
        }
        __syncthreads();
        #pragma unroll
        for (int kk = 0; kk < 16; kk++) {
            float a0 = As[r0 + 0][kk];
            float a1 = As[r0 + 1][kk];
            float a2 = As[r0 + 2][kk];
            float a3 = As[r0 + 3][kk];
            float4 bb = *(const float4*)&Ws[kk][c0];
            acc[0][0] += a0 * bb.x; acc[0][1] += a0 * bb.y; acc[0][2] += a0 * bb.z; acc[0][3] += a0 * bb.w;
            acc[1][0] += a1 * bb.x; acc[1][1] += a1 * bb.y; acc[1][2] += a1 * bb.z; acc[1][3] += a1 * bb.w;
            acc[2][0] += a2 * bb.x; acc[2][1] += a2 * bb.y; acc[2][2] += a2 * bb.z; acc[2][3] += a2 * bb.w;
            acc[3][0] += a3 * bb.x; acc[3][1] += a3 * bb.y; acc[3][2] += a3 * bb.z; acc[3][3] += a3 * bb.w;
        }
        __syncthreads();
    }

    #pragma unroll
    for (int i = 0; i < 4; i++) {
        int gr = rowBase + r0 + i;
        #pragma unroll
        for (int j = 0; j < 4; j++) {
            int gc = colBase + c0 + j;
            if (gc < N) {
                float val = acc[i][j];
                if (flags & 1) val += bias[gc];
                if (flags & 2) val = fmaxf(val, 0.f);
                if (flags & 4) val += resid[(size_t)gr * N + gc];
                C[(size_t)gr * N + gc] = val;
            }
        }
    }
}

// ---------------- attention scores: S = Q K^T * scale (causal; write only valid) ----------------
// grid (ct=16, rt=16, bh=32); writes into per-layer slab of d_out.
__global__ void scores_kernel(const float* __restrict__ q,
                              const float* __restrict__ k,
                              float* __restrict__ attn) {
    int bh = blockIdx.z;
    int b = bh >> 3, h = bh & 7;
    int rt = blockIdx.y, ct = blockIdx.x;
    if (ct > rt) return;   // fully masked tile: softmax writes the zeros
    __shared__ float Qs[64][65];   // [r][d]
    __shared__ float Kt[64][68];   // [d][c]
    int tid = threadIdx.x;
    int rowBase = rt * 64, colBase = ct * 64;
    const float* qb = q + ((size_t)(b * T + rowBase)) * E + h * HD;
    const float* kb = k + ((size_t)(b * T + colBase)) * E + h * HD;
    #pragma unroll
    for (int i = 0; i < 16; i++) {
        int e = tid + i * 256;
        int d = e & 63, r = e >> 6;
        Qs[r][d] = qb[(size_t)r * E + d];
        Kt[d][r] = kb[(size_t)r * E + d];
    }
    __syncthreads();
    int r0 = (tid >> 4) * 4, c0 = (tid & 15) * 4;
    float acc[4][4] = {};
    #pragma unroll 16
    for (int d = 0; d < 64; d++) {
        float a0 = Qs[r0 + 0][d];
        float a1 = Qs[r0 + 1][d];
        float a2 = Qs[r0 + 2][d];
        float a3 = Qs[r0 + 3][d];
        float4 bb = *(const float4*)&Kt[d][c0];
        acc[0][0] += a0 * bb.x; acc[0][1] += a0 * bb.y; acc[0][2] += a0 * bb.z; acc[0][3] += a0 * bb.w;
        acc[1][0] += a1 * bb.x; acc[1][1] += a1 * bb.y; acc[1][2] += a1 * bb.z; acc[1][3] += a1 * bb.w;
        acc[2][0] += a2 * bb.x; acc[2][1] += a2 * bb.y; acc[2][2] += a2 * bb.z; acc[2][3] += a2 * bb.w;
        acc[3][0] += a3 * bb.x; acc[3][1] += a3 * bb.y; acc[3][2] += a3 * bb.z; acc[3][3] += a3 * bb.w;
    }
    const float sc = 0.125f;   // 1/sqrt(64)
    float* ab = attn + ((size_t)bh * T + rowBase) * T + colBase;
    #pragma unroll
    for (int i = 0; i < 4; i++) {
        int gr = rowBase + r0 + i;
        #pragma unroll
        for (int j = 0; j < 4; j++) {
            int gc = colBase + c0 + j;
            if (gc <= gr) ab[(size_t)(r0 + i) * T + c0 + j] = acc[i][j] * sc;
        }
    }
}

// ---------------- causal softmax in place; zeros masked tail ----------------
__global__ void softmax_kernel(float* __restrict__ attn) {
    int row = blockIdx.x;                  // over B*H*T
    int t = row & (T - 1);
    float* p = attn + (size_t)row * T;
    int valid = t + 1;
    __shared__ float red[256];
    int tid = threadIdx.x;
    float m = -1e30f;
    for (int j = tid; j < valid; j += 256) m = fmaxf(m, p[j]);
    red[tid] = m;
    __syncthreads();
    #pragma unroll
    for (int s = 128; s > 0; s >>= 1) {
        if (tid < s) red[tid] = fmaxf(red[tid], red[tid + s]);
        __syncthreads();
    }
    m = red[0];
    __syncthreads();
    float sum = 0.f;
    for (int j = tid; j < valid; j += 256) {
        float ev = __expf(p[j] - m);
        p[j] = ev;
        sum += ev;
    }
    red[tid] = sum;
    __syncthreads();
    #pragma unroll
    for (int s = 128; s > 0; s >>= 1) {
        if (tid < s) red[tid] += red[tid + s];
        __syncthreads();
    }
    float inv = 1.0f / red[0];
    for (int j = tid; j < valid; j += 256) p[j] *= inv;
    for (int j = valid + tid; j < T; j += 256) p[j] = 0.f;
}

// ---------------- Y = P @ V per (b,h); exploits causality (skip zero K-chunks) ----------------
// grid (rt=16, bh=32)
__global__ void av_kernel(const float* __restrict__ attn,
                          const float* __restrict__ v,
                          float* __restrict__ y) {
    int bh = blockIdx.y;
    int b = bh >> 3, h = bh & 7;
    int rt = blockIdx.x;
    int rowBase = rt * 64;
    __shared__ float Ps[64][65];   // [r][kk]
    __shared__ float Vs[64][68];   // [kk][c]
    int tid = threadIdx.x;
    int r0 = (tid >> 4) * 4, c0 = (tid & 15) * 4;
    float acc[4][4] = {};
    const float* ab = attn + ((size_t)bh * T + rowBase) * T;
    const float* vb = v + ((size_t)(b * T)) * E + h * HD;
    int kend = rowBase + 64;
    for (int k0 = 0; k0 < kend; k0 += 64) {
        #pragma unroll
        for (int i = 0; i < 16; i++) {
            int e = tid + i * 256;
            int cc = e & 63, rr = e >> 6;
            Ps[rr][cc] = ab[(size_t)rr * T + k0 + cc];
            Vs[rr][cc] = vb[(size_t)(k0 + rr) * E + cc];
        }
        __syncthreads();
        #pragma unroll 16
        for (int kk = 0; kk < 64; kk++) {
            float a0 = Ps[r0 + 0][kk];
            float a1 = Ps[r0 + 1][kk];
            float a2 = Ps[r0 + 2][kk];
            float a3 = Ps[r0 + 3][kk];
            float4 bb = *(const float4*)&Vs[kk][c0];
            acc[0][0] += a0 * bb.x; acc[0][1] += a0 * bb.y; acc[0][2] += a0 * bb.z; acc[0][3] += a0 * bb.w;
            acc[1][0] += a1 * bb.x; acc[1][1] += a1 * bb.y; acc[1][2] += a1 * bb.z; acc[1][3] += a1 * bb.w;
            acc[2][0] += a2 * bb.x; acc[2][1] += a2 * bb.y; acc[2][2] += a2 * bb.z; acc[2][3] += a2 * bb.w;
            acc[3][0] += a3 * bb.x; acc[3][1] += a3 * bb.y; acc[3][2] += a3 * bb.z; acc[3][3] += a3 * bb.w;
        }
        __syncthreads();
    }
    float* yb = y + ((size_t)(b * T + rowBase)) * E + h * HD;
    #pragma unroll
    for (int i = 0; i < 4; i++)
        #pragma unroll
        for (int j = 0; j < 4; j++)
            yb[(size_t)(r0 + i) * E + c0 + j] = acc[i][j];
}

// ---------------- launch ----------------
extern "C" void kernel_launch(void* const* d_in, const int* in_sizes, int n_in,
                              void* d_out, int out_size) {
    const int*   idx  = (const int*)  d_in[0];
    const float* tok  = (const float*)d_in[1];
    const float* pos  = (const float*)d_in[2];
    const float* ln1g = (const float*)d_in[3];
    const float* ln1b = (const float*)d_in[4];
    const float* Wq   = (const float*)d_in[5];
    const float* Wk   = (const float*)d_in[6];
    const float* Wv   = (const float*)d_in[7];
    const float* Wo   = (const float*)d_in[8];
    const float* bo   = (const float*)d_in[9];
    const float* ln2g = (const float*)d_in[10];
    const float* ln2b = (const float*)d_in[11];
    const float* W1   = (const float*)d_in[12];
    const float* b1   = (const float*)d_in[13];
    const float* W2   = (const float*)d_in[14];
    const float* b2   = (const float*)d_in[15];
    const float* lnfg = (const float*)d_in[16];
    const float* lnfb = (const float*)d_in[17];
    const float* Wlm  = (const float*)d_in[18];

    float* out = (float*)d_out;
    float* logits = out;                               // (B,T,V)
    float* attn_all = out + (size_t)B * T * V;         // (L,B,H,T,T)

    float *x, *h, *q, *kk, *v, *y, *f;
    cudaGetSymbolAddress((void**)&x,  g_x);
    cudaGetSymbolAddress((void**)&h,  g_h);
    cudaGetSymbolAddress((void**)&q,  g_q);
    cudaGetSymbolAddress((void**)&kk, g_k);
    cudaGetSymbolAddress((void**)&v,  g_v);
    cudaGetSymbolAddress((void**)&y,  g_y);
    cudaGetSymbolAddress((void**)&f,  g_f);

    embed_kernel<<<BT * E / 256, 256>>>(idx, tok, pos, x);

    dim3 gE((E + 63) / 64, BT / 64);
    dim3 gH((HID + 63) / 64, BT / 64);
    dim3 gV((V + 63) / 64, BT / 64);

    for (int l = 0; l < L; l++) {
        float* attn_l = attn_all + (size_t)l * B * H * T * T;
        ln_kernel<<<BT, 256>>>(x, ln1g + l * E, ln1b + l * E, h);
        gemm_kernel<<<gE, 256>>>(h, Wq + (size_t)l * E * E, nullptr, nullptr, q,  BT, E, E, 0);
        gemm_kernel<<<gE, 256>>>(h, Wk + (size_t)l * E * E, nullptr, nullptr, kk, BT, E, E, 0);
        gemm_kernel<<<gE, 256>>>(h, Wv + (size_t)l * E * E, nullptr, nullptr, v,  BT, E, E, 0);
        scores_kernel<<<dim3(T / 64, T / 64, B * H), 256>>>(q, kk, attn_l);
        softmax_kernel<<<B * H * T, 256>>>(attn_l);
        av_kernel<<<dim3(T / 64, B * H), 256>>>(attn_l, v, y);
        gemm_kernel<<<gE, 256>>>(y, Wo + (size_t)l * E * E, bo + l * E, x, x, BT, E, E, 1 | 4);
        ln_kernel<<<BT, 256>>>(x, ln2g + l * E, ln2b + l * E, h);
        gemm_kernel<<<gH, 256>>>(h, W1 + (size_t)l * E * HID, b1 + l * HID, nullptr, f, BT, HID, E, 1 | 2);
        gemm_kernel<<<gE, 256>>>(f, W2 + (size_t)l * HID * E, b2 + l * E, x, x, BT, E, HID, 1 | 4);
    }
    ln_kernel<<<BT, 256>>>(x, lnfg, lnfb, h);
    gemm_kernel<<<gV, 256>>>(h, Wlm, nullptr, nullptr, logits, BT, V, E, 0);
}

// round 17
// speedup vs baseline: 1.9290x; 1.9271x over previous
#include <cuda_runtime.h>
#include <cstdint>

#define B 4
#define T 1024
#define E 512
#define H 8
#define L 4
#define V 32000
#define HID 100
#define HD 64
#define BT (B*T)

// ---------------- scratch (no allocations allowed) ----------------
__device__ __align__(16) float g_x[BT * E];
__device__ __align__(16) float g_h[BT * E];
__device__ __align__(16) float g_q[BT * E];
__device__ __align__(16) float g_k[BT * E];
__device__ __align__(16) float g_v[BT * E];
__device__ __align__(16) float g_y[BT * E];
__device__ __align__(16) float g_f[BT * HID];
__device__ __align__(16) unsigned int g_WlmT[(size_t)V * E];   // tf32-rounded Wlm^T [V][E]

// ============ helpers ============
__device__ __forceinline__ uint32_t smem_u32(const void* p) {
    uint32_t a;
    asm("{ .reg .u64 t; cvta.to.shared.u64 t, %1; cvt.u32.u64 %0, t; }" : "=r"(a) : "l"(p));
    return a;
}
__device__ __forceinline__ unsigned int f32_to_tf32_rna(float x) {
    unsigned int u;
    asm("cvt.rna.tf32.f32 %0, %1;" : "=r"(u) : "f"(x));
    return u;
}
__device__ __forceinline__ void mma_tf32(float* c, const uint32_t* a, const uint32_t* b) {
    asm volatile(
        "mma.sync.aligned.m16n8k8.row.col.f32.tf32.tf32.f32 "
        "{%0,%1,%2,%3}, {%4,%5,%6,%7}, {%8,%9}, {%0,%1,%2,%3};"
        : "+f"(c[0]), "+f"(c[1]), "+f"(c[2]), "+f"(c[3])
        : "r"(a[0]), "r"(a[1]), "r"(a[2]), "r"(a[3]), "r"(b[0]), "r"(b[1]));
}
// swizzled LDS read: buf = 128 rows x 8 16B-chunks; k in floats [0,32)
__device__ __forceinline__ uint32_t ldsu(const uint4* buf, int row, int k) {
    return ((const uint32_t*)(buf + row * 8 + ((k >> 2) ^ (row & 7))))[k & 3];
}
// cp.async one 128-row x 32-float chunk (row stride 512 floats) into swizzled smem
__device__ __forceinline__ void stage_tile(uint32_t sdst, const unsigned int* gsrc, int tid) {
    #pragma unroll
    for (int i = 0; i < 4; i++) {
        int idx = tid + i * 256;            // 0..1023 16B transfers
        int r = idx >> 3, q = idx & 7;
        const void* src = gsrc + (size_t)r * 512 + q * 4;
        uint32_t dst = sdst + (uint32_t)((r * 8 + (q ^ (r & 7))) << 4);
        asm volatile("cp.async.ca.shared.global [%0], [%1], 16;" :: "r"(dst), "l"(src));
    }
}

// ---------------- embedding: x = tok_emb[idx] + pos_emb ----------------
__global__ void embed_kernel(const int* __restrict__ idx,
                             const float* __restrict__ tok,
                             const float* __restrict__ pos,
                             float* __restrict__ x) {
    int i = blockIdx.x * 256 + threadIdx.x;
    int e = i & (E - 1);
    int bt = i >> 9;
    int t = bt & (T - 1);
    x[i] = tok[(size_t)idx[bt] * E + e] + pos[t * E + e];
}

// ---------------- layernorm: one block per row of E=512 ----------------
__global__ void ln_kernel(const float* __restrict__ x,
                          const float* __restrict__ g,
                          const float* __restrict__ b,
                          float* __restrict__ o) {
    int row = blockIdx.x;
    int tid = threadIdx.x;
    const float* xr = x + (size_t)row * E;
    float v0 = xr[tid], v1 = xr[tid + 256];
    __shared__ float red[256];
    red[tid] = v0 + v1;
    __syncthreads();
    #pragma unroll
    for (int s = 128; s > 0; s >>= 1) {
        if (tid < s) red[tid] += red[tid + s];
        __syncthreads();
    }
    float m = red[0] * (1.0f / E);
    __syncthreads();
    float d0 = v0 - m, d1 = v1 - m;
    red[tid] = d0 * d0 + d1 * d1;
    __syncthreads();
    #pragma unroll
    for (int s = 128; s > 0; s >>= 1) {
        if (tid < s) red[tid] += red[tid + s];
        __syncthreads();
    }
    float rstd = rsqrtf(red[0] * (1.0f / E) + 1e-5f);
    float* orow = o + (size_t)row * E;
    orow[tid]       = d0 * rstd * g[tid]       + b[tid];
    orow[tid + 256] = d1 * rstd * g[tid + 256] + b[tid + 256];
}

// ---------------- generic tiled GEMM (fp32 SIMT, for layer GEMMs) ----------------
__global__ void gemm_kernel(const float* __restrict__ A,
                            const float* __restrict__ W,
                            const float* __restrict__ bias,
                            const float* __restrict__ resid,
                            float* __restrict__ C,
                            int M, int N, int K, int flags) {
    __shared__ float As[64][17];
    __shared__ float Ws[16][64];
    int tid = threadIdx.x;
    int rowBase = blockIdx.y * 64;
    int colBase = blockIdx.x * 64;
    int r0 = (tid >> 4) * 4;
    int c0 = (tid & 15) * 4;
    float acc[4][4] = {};

    for (int k0 = 0; k0 < K; k0 += 16) {
        #pragma unroll
        for (int i = 0; i < 4; i++) {
            int e = tid + i * 256;
            int r = e >> 4, kk = e & 15;
            int gk = k0 + kk;
            As[r][kk] = (gk < K) ? A[(size_t)(rowBase + r) * K + gk] : 0.f;
        }
        #pragma unroll
        for (int i = 0; i < 4; i++) {
            int e = tid + i * 256;
            int kk = e >> 6, cc = e & 63;
            int gk = k0 + kk, gc = colBase + cc;
            Ws[kk][cc] = (gk < K && gc < N) ? W[(size_t)gk * N + gc] : 0.f;
        }
        __syncthreads();
        #pragma unroll
        for (int kk = 0; kk < 16; kk++) {
            float a0 = As[r0 + 0][kk];
            float a1 = As[r0 + 1][kk];
            float a2 = As[r0 + 2][kk];
            float a3 = As[r0 + 3][kk];
            float4 bb = *(const float4*)&Ws[kk][c0];
            acc[0][0] += a0 * bb.x; acc[0][1] += a0 * bb.y; acc[0][2] += a0 * bb.z; acc[0][3] += a0 * bb.w;
            acc[1][0] += a1 * bb.x; acc[1][1] += a1 * bb.y; acc[1][2] += a1 * bb.z; acc[1][3] += a1 * bb.w;
            acc[2][0] += a2 * bb.x; acc[2][1] += a2 * bb.y; acc[2][2] += a2 * bb.z; acc[2][3] += a2 * bb.w;
            acc[3][0] += a3 * bb.x; acc[3][1] += a3 * bb.y; acc[3][2] += a3 * bb.z; acc[3][3] += a3 * bb.w;
        }
        __syncthreads();
    }

    #pragma unroll
    for (int i = 0; i < 4; i++) {
        int gr = rowBase + r0 + i;
        #pragma unroll
        for (int j = 0; j < 4; j++) {
            int gc = colBase + c0 + j;
            if (gc < N) {
                float val = acc[i][j];
                if (flags & 1) val += bias[gc];
                if (flags & 2) val = fmaxf(val, 0.f);
                if (flags & 4) val += resid[(size_t)gr * N + gc];
                C[(size_t)gr * N + gc] = val;
            }
        }
    }
}

// ---------------- attention scores ----------------
__global__ void scores_kernel(const float* __restrict__ q,
                              const float* __restrict__ k,
                              float* __restrict__ attn) {
    int bh = blockIdx.z;
    int b = bh >> 3, h = bh & 7;
    int rt = blockIdx.y, ct = blockIdx.x;
    if (ct > rt) return;
    __shared__ float Qs[64][65];
    __shared__ float Kt[64][68];
    int tid = threadIdx.x;
    int rowBase = rt * 64, colBase = ct * 64;
    const float* qb = q + ((size_t)(b * T + rowBase)) * E + h * HD;
    const float* kb = k + ((size_t)(b * T + colBase)) * E + h * HD;
    #pragma unroll
    for (int i = 0; i < 16; i++) {
        int e = tid + i * 256;
        int d = e & 63, r = e >> 6;
        Qs[r][d] = qb[(size_t)r * E + d];
        Kt[d][r] = kb[(size_t)r * E + d];
    }
    __syncthreads();
    int r0 = (tid >> 4) * 4, c0 = (tid & 15) * 4;
    float acc[4][4] = {};
    #pragma unroll 16
    for (int d = 0; d < 64; d++) {
        float a0 = Qs[r0 + 0][d];
        float a1 = Qs[r0 + 1][d];
        float a2 = Qs[r0 + 2][d];
        float a3 = Qs[r0 + 3][d];
        float4 bb = *(const float4*)&Kt[d][c0];
        acc[0][0] += a0 * bb.x; acc[0][1] += a0 * bb.y; acc[0][2] += a0 * bb.z; acc[0][3] += a0 * bb.w;
        acc[1][0] += a1 * bb.x; acc[1][1] += a1 * bb.y; acc[1][2] += a1 * bb.z; acc[1][3] += a1 * bb.w;
        acc[2][0] += a2 * bb.x; acc[2][1] += a2 * bb.y; acc[2][2] += a2 * bb.z; acc[2][3] += a2 * bb.w;
        acc[3][0] += a3 * bb.x; acc[3][1] += a3 * bb.y; acc[3][2] += a3 * bb.z; acc[3][3] += a3 * bb.w;
    }
    const float sc = 0.125f;
    float* ab = attn + ((size_t)bh * T + rowBase) * T + colBase;
    #pragma unroll
    for (int i = 0; i < 4; i++) {
        int gr = rowBase + r0 + i;
        #pragma unroll
        for (int j = 0; j < 4; j++) {
            int gc = colBase + c0 + j;
            if (gc <= gr) ab[(size_t)(r0 + i) * T + c0 + j] = acc[i][j] * sc;
        }
    }
}

// ---------------- causal softmax ----------------
__global__ void softmax_kernel(float* __restrict__ attn) {
    int row = blockIdx.x;
    int t = row & (T - 1);
    float* p = attn + (size_t)row * T;
    int valid = t + 1;
    __shared__ float red[256];
    int tid = threadIdx.x;
    float m = -1e30f;
    for (int j = tid; j < valid; j += 256) m = fmaxf(m, p[j]);
    red[tid] = m;
    __syncthreads();
    #pragma unroll
    for (int s = 128; s > 0; s >>= 1) {
        if (tid < s) red[tid] = fmaxf(red[tid], red[tid + s]);
        __syncthreads();
    }
    m = red[0];
    __syncthreads();
    float sum = 0.f;
    for (int j = tid; j < valid; j += 256) {
        float ev = __expf(p[j] - m);
        p[j] = ev;
        sum += ev;
    }
    red[tid] = sum;
    __syncthreads();
    #pragma unroll
    for (int s = 128; s > 0; s >>= 1) {
        if (tid < s) red[tid] += red[tid + s];
        __syncthreads();
    }
    float inv = 1.0f / red[0];
    for (int j = tid; j < valid; j += 256) p[j] *= inv;
    for (int j = valid + tid; j < T; j += 256) p[j] = 0.f;
}

// ---------------- Y = P @ V ----------------
__global__ void av_kernel(const float* __restrict__ attn,
                          const float* __restrict__ v,
                          float* __restrict__ y) {
    int bh = blockIdx.y;
    int b = bh >> 3, h = bh & 7;
    int rt = blockIdx.x;
    int rowBase = rt * 64;
    __shared__ float Ps[64][65];
    __shared__ float Vs[64][68];
    int tid = threadIdx.x;
    int r0 = (tid >> 4) * 4, c0 = (tid & 15) * 4;
    float acc[4][4] = {};
    const float* ab = attn + ((size_t)bh * T + rowBase) * T;
    const float* vb = v + ((size_t)(b * T)) * E + h * HD;
    int kend = rowBase + 64;
    for (int k0 = 0; k0 < kend; k0 += 64) {
        #pragma unroll
        for (int i = 0; i < 16; i++) {
            int e = tid + i * 256;
            int cc = e & 63, rr = e >> 6;
            Ps[rr][cc] = ab[(size_t)rr * T + k0 + cc];
            Vs[rr][cc] = vb[(size_t)(k0 + rr) * E + cc];
        }
        __syncthreads();
        #pragma unroll 16
        for (int kk = 0; kk < 64; kk++) {
            float a0 = Ps[r0 + 0][kk];
            float a1 = Ps[r0 + 1][kk];
            float a2 = Ps[r0 + 2][kk];
            float a3 = Ps[r0 + 3][kk];
            float4 bb = *(const float4*)&Vs[kk][c0];
            acc[0][0] += a0 * bb.x; acc[0][1] += a0 * bb.y; acc[0][2] += a0 * bb.z; acc[0][3] += a0 * bb.w;
            acc[1][0] += a1 * bb.x; acc[1][1] += a1 * bb.y; acc[1][2] += a1 * bb.z; acc[1][3] += a1 * bb.w;
            acc[2][0] += a2 * bb.x; acc[2][1] += a2 * bb.y; acc[2][2] += a2 * bb.z; acc[2][3] += a2 * bb.w;
            acc[3][0] += a3 * bb.x; acc[3][1] += a3 * bb.y; acc[3][2] += a3 * bb.z; acc[3][3] += a3 * bb.w;
        }
        __syncthreads();
    }
    float* yb = y + ((size_t)(b * T + rowBase)) * E + h * HD;
    #pragma unroll
    for (int i = 0; i < 4; i++)
        #pragma unroll
        for (int j = 0; j < 4; j++)
            yb[(size_t)(r0 + i) * E + c0 + j] = acc[i][j];
}

// ---------------- Wlm transpose + tf32 round: WlmT[v][e] = tf32(Wlm[e][v]) ----------------
__global__ void transpose_wlm_kernel(const float* __restrict__ Wlm,
                                     unsigned int* __restrict__ WlmT) {
    __shared__ float tile[32][33];
    int vb = blockIdx.x * 32, eb = blockIdx.y * 32;
    int tx = threadIdx.x, ty = threadIdx.y;
    #pragma unroll
    for (int j = 0; j < 32; j += 8)
        tile[ty + j][tx] = Wlm[(size_t)(eb + ty + j) * V + vb + tx];
    __syncthreads();
    #pragma unroll
    for (int j = 0; j < 32; j += 8)
        WlmT[(size_t)(vb + ty + j) * E + eb + tx] = f32_to_tf32_rna(tile[tx][ty + j]);
}

// ---------------- elementwise tf32 round ----------------
__global__ void round_tf32_kernel(const float* __restrict__ in,
                                  unsigned int* __restrict__ out) {
    int i = blockIdx.x * 256 + threadIdx.x;
    out[i] = f32_to_tf32_rna(in[i]);
}

// ---------------- logits GEMM via mma.sync tf32 (baseline ISA, works on sm_103) ----
// C[4096, 32000] = A[4096,512] @ WlmT^T, A and WlmT both K-major tf32 (pre-rounded).
// CTA tile 128x128, 8 warps = 2(M) x 4(N), warp tile 64x32, mma m16n8k8.
// cp.async double-buffered staging, XOR-swizzled 16B chunks, conflict-free LDS.
__global__ void __launch_bounds__(256) lm_gemm_mma(const unsigned int* __restrict__ Aq,
                                                    const unsigned int* __restrict__ Bq,
                                                    float* __restrict__ Cout) {
    extern __shared__ char smem[];
    uint32_t sbase = smem_u32(smem);
    int tid = threadIdx.x, lane = tid & 31, wid = tid >> 5;
    int warpM = wid & 1, warpN = wid >> 1;
    int rowBase = blockIdx.x * 128, colBase = blockIdx.y * 128;

    const unsigned int* Ag = Aq + (size_t)rowBase * 512;
    const unsigned int* Bg = Bq + (size_t)colBase * 512;

    float acc[4][4][4] = {};

    // smem layout: A buf0 @0, A buf1 @16K, B buf0 @32K, B buf1 @48K
    stage_tile(sbase, Ag, tid);
    stage_tile(sbase + 32768, Bg, tid);
    asm volatile("cp.async.commit_group;" ::: "memory");

    for (int c = 0; c < 16; c++) {
        if (c < 15) {
            uint32_t boff = (uint32_t)((c + 1) & 1) * 16384;
            stage_tile(sbase + boff, Ag + (c + 1) * 32, tid);
            stage_tile(sbase + 32768 + boff, Bg + (c + 1) * 32, tid);
            asm volatile("cp.async.commit_group;" ::: "memory");
            asm volatile("cp.async.wait_group 1;" ::: "memory");
        } else {
            asm volatile("cp.async.wait_group 0;" ::: "memory");
        }
        __syncthreads();
        const uint4* bufA = (const uint4*)smem + (c & 1) * 1024;
        const uint4* bufB = (const uint4*)smem + 2048 + (c & 1) * 1024;
        #pragma unroll
        for (int ks = 0; ks < 4; ks++) {
            int kk = ks * 8 + (lane & 3);
            uint32_t a[4][4], bf[4][2];
            #pragma unroll
            for (int mf = 0; mf < 4; mf++) {
                int m = warpM * 64 + mf * 16 + (lane >> 2);
                a[mf][0] = ldsu(bufA, m,     kk);
                a[mf][1] = ldsu(bufA, m + 8, kk);
                a[mf][2] = ldsu(bufA, m,     kk + 4);
                a[mf][3] = ldsu(bufA, m + 8, kk + 4);
            }
            #pragma unroll
            for (int nf = 0; nf < 4; nf++) {
                int n = warpN * 32 + nf * 8 + (lane >> 2);
                bf[nf][0] = ldsu(bufB, n, kk);
                bf[nf][1] = ldsu(bufB, n, kk + 4);
            }
            #pragma unroll
            for (int mf = 0; mf < 4; mf++)
                #pragma unroll
                for (int nf = 0; nf < 4; nf++)
                    mma_tf32(acc[mf][nf], a[mf], bf[nf]);
        }
        __syncthreads();
    }

    // epilogue: direct global stores (float2 = the 2 contiguous cols of each C frag)
    int rw = rowBase + warpM * 64 + (lane >> 2);
    int cw = colBase + warpN * 32 + 2 * (lane & 3);
    #pragma unroll
    for (int mf = 0; mf < 4; mf++) {
        #pragma unroll
        for (int nf = 0; nf < 4; nf++) {
            size_t base = (size_t)(rw + mf * 16) * V + cw + nf * 8;
            *(float2*)&Cout[base]             = make_float2(acc[mf][nf][0], acc[mf][nf][1]);
            *(float2*)&Cout[base + (size_t)8 * V] = make_float2(acc[mf][nf][2], acc[mf][nf][3]);
        }
    }
}

// ---------------- launch ----------------
extern "C" void kernel_launch(void* const* d_in, const int* in_sizes, int n_in,
                              void* d_out, int out_size) {
    const int*   idx  = (const int*)  d_in[0];
    const float* tok  = (const float*)d_in[1];
    const float* pos  = (const float*)d_in[2];
    const float* ln1g = (const float*)d_in[3];
    const float* ln1b = (const float*)d_in[4];
    const float* Wq   = (const float*)d_in[5];
    const float* Wk   = (const float*)d_in[6];
    const float* Wv   = (const float*)d_in[7];
    const float* Wo   = (const float*)d_in[8];
    const float* bo   = (const float*)d_in[9];
    const float* ln2g = (const float*)d_in[10];
    const float* ln2b = (const float*)d_in[11];
    const float* W1   = (const float*)d_in[12];
    const float* b1   = (const float*)d_in[13];
    const float* W2   = (const float*)d_in[14];
    const float* b2   = (const float*)d_in[15];
    const float* lnfg = (const float*)d_in[16];
    const float* lnfb = (const float*)d_in[17];
    const float* Wlm  = (const float*)d_in[18];

    float* out = (float*)d_out;
    float* logits = out;                               // (B,T,V)
    float* attn_all = out + (size_t)B * T * V;         // (L,B,H,T,T)

    float *x, *h, *q, *kk, *v, *y, *f;
    unsigned int* wlmt;
    cudaGetSymbolAddress((void**)&x,  g_x);
    cudaGetSymbolAddress((void**)&h,  g_h);
    cudaGetSymbolAddress((void**)&q,  g_q);
    cudaGetSymbolAddress((void**)&kk, g_k);
    cudaGetSymbolAddress((void**)&v,  g_v);
    cudaGetSymbolAddress((void**)&y,  g_y);
    cudaGetSymbolAddress((void**)&f,  g_f);
    cudaGetSymbolAddress((void**)&wlmt, g_WlmT);

    cudaFuncSetAttribute(lm_gemm_mma, cudaFuncAttributeMaxDynamicSharedMemorySize, 65536);

    // Wlm transpose+round is independent of the network; do it first.
    transpose_wlm_kernel<<<dim3(V / 32, E / 32), dim3(32, 8)>>>(Wlm, wlmt);

    embed_kernel<<<BT * E / 256, 256>>>(idx, tok, pos, x);

    dim3 gE((E + 63) / 64, BT / 64);
    dim3 gH((HID + 63) / 64, BT / 64);

    for (int l = 0; l < L; l++) {
        float* attn_l = attn_all + (size_t)l * B * H * T * T;
        ln_kernel<<<BT, 256>>>(x, ln1g + l * E, ln1b + l * E, h);
        gemm_kernel<<<gE, 256>>>(h, Wq + (size_t)l * E * E, nullptr, nullptr, q,  BT, E, E, 0);
        gemm_kernel<<<gE, 256>>>(h, Wk + (size_t)l * E * E, nullptr, nullptr, kk, BT, E, E, 0);
        gemm_kernel<<<gE, 256>>>(h, Wv + (size_t)l * E * E, nullptr, nullptr, v,  BT, E, E, 0);
        scores_kernel<<<dim3(T / 64, T / 64, B * H), 256>>>(q, kk, attn_l);
        softmax_kernel<<<B * H * T, 256>>>(attn_l);
        av_kernel<<<dim3(T / 64, B * H), 256>>>(attn_l, v, y);
        gemm_kernel<<<gE, 256>>>(y, Wo + (size_t)l * E * E, bo + l * E, x, x, BT, E, E, 1 | 4);
        ln_kernel<<<BT, 256>>>(x, ln2g + l * E, ln2b + l * E, h);
        gemm_kernel<<<gH, 256>>>(h, W1 + (size_t)l * E * HID, b1 + l * HID, nullptr, f, BT, HID, E, 1 | 2);
        gemm_kernel<<<gE, 256>>>(f, W2 + (size_t)l * HID * E, b2 + l * E, x, x, BT, E, HID, 1 | 4);
    }
    ln_kernel<<<BT, 256>>>(x, lnfg, lnfb, h);
    round_tf32_kernel<<<BT * E / 256, 256>>>(h, (unsigned int*)q);   // q scratch is free here
    lm_gemm_mma<<<dim3(BT / 128, V / 128), 256, 65536>>>((const unsigned int*)q, wlmt, logits);
}